// round 5
// baseline (speedup 1.0000x reference)
#include <cuda_runtime.h>
#include <math.h>

#define NT    512
#define NGRID 2048
#define NXF   16
#define HID   64
#define DLY   4
#define NG    32     // grid cells per block
#define NTHR  256
#define TCH   8      // time chunks
#define CH    64     // emission steps per chunk
#define WPAD  68     // padded weight row (bank-conflict-free float4 loads)

struct __align__(16) SmemLayout {
    float Win[NXF][WPAD];   // W_in[k][j]
    float Wxh[HID][WPAD];   // W_xh[k][j]
    float Whh[HID][WPAD];   // W_hh[k][j]
    float bin[HID];
    float bh[HID];
    float Wout[HID];
    float s1[HID][NG];      // states, transposed [hidden][cell]
    float s2[HID][NG];
    float s3[HID][NG];
    float Us[HID][NG];      // U transposed [hidden][cell]
    float xb[2][NXF][NG];   // double-buffered x tile, transposed [feat][cell]
    float part[16][NG];     // y partial sums per j-group
};

__device__ __forceinline__ float fast_tanh(float v) {
    // tanh(x) = 1 - 2/(1+exp(2x)); exact identity, only MUFU rounding (~1e-6 abs).
    // Overflow-safe: exp->inf gives 1, exp->0 gives -1.
    float e = __expf(2.0f * v);
    return 1.0f - __fdividef(2.0f, e + 1.0f);
}

extern "C" __global__ void __launch_bounds__(NTHR, 2)
narx_stream_kernel(const float* __restrict__ x,
                   const float* __restrict__ W_in,
                   const float* __restrict__ b_in,
                   const float* __restrict__ W_xh,
                   const float* __restrict__ W_hh,
                   const float* __restrict__ b_h,
                   const float* __restrict__ W_out,
                   const float* __restrict__ b_out,
                   float* __restrict__ out)
{
    extern __shared__ __align__(16) char smraw[];
    SmemLayout& sm = *reinterpret_cast<SmemLayout*>(smraw);

    const int tid = threadIdx.x;
    const int mg  = tid & 15;      // 16 m-groups of 2 cells
    const int jg  = tid >> 4;      // 16 j-groups of 4 hidden
    const int m0  = mg << 1;
    const int j0  = jg << 2;
    const int cell0 = blockIdx.x * NG;
    const int tb  = blockIdx.y * CH;          // first emitted t of this chunk
    const int te  = min(tb + CH, NT - 1);     // one past last emitted t (t<=510)
    const int ts  = max(tb - (DLY - 1), 0);   // 3-step warm-up halo
    const int emit_lo = max(tb, DLY - 1);     // t >= 3

    // ---- load weights / biases into shared ----
    for (int i = tid; i < NXF * HID; i += NTHR) sm.Win[i >> 6][i & 63] = W_in[i];
    for (int i = tid; i < HID * HID; i += NTHR) sm.Wxh[i >> 6][i & 63] = W_xh[i];
    for (int i = tid; i < HID * HID; i += NTHR) sm.Whh[i >> 6][i & 63] = W_hh[i];
    if (tid < HID) {
        sm.bin[tid]  = b_in[tid];
        sm.bh[tid]   = b_h[tid];
        sm.Wout[tid] = W_out[tid];
    }
    for (int i = tid; i < HID * NG; i += NTHR) {
        int k = i >> 5, m = i & (NG - 1);
        sm.s1[k][m] = 0.f; sm.s2[k][m] = 0.f; sm.s3[k][m] = 0.f;
    }
    const float bout = b_out[0];

    // ---- preload x[ts] tile (NG*NXF = 512 floats) ----
    {
        const float* xrow = x + (ts * NGRID + cell0) * NXF;
        int l0 = tid, l1 = tid + NTHR;
        sm.xb[ts & 1][l0 & 15][l0 >> 4] = xrow[l0];
        sm.xb[ts & 1][l1 & 15][l1 >> 4] = xrow[l1];
    }
    __syncthreads();

    for (int t = ts; t < te; ++t) {
        const int buf = t & 1;

        // prefetch next x row into registers (STS before sync1, read after sync2)
        float pf0 = 0.f, pf1 = 0.f;
        const bool haveNext = (t + 1 < te);
        if (haveNext) {
            const float* xrow = x + ((t + 1) * NGRID + cell0) * NXF;
            pf0 = xrow[tid];
            pf1 = xrow[tid + NTHR];
        }

        // ---- U = relu(x[t] @ W_in + b_in), K = 16 ----
        float u[8];
        #pragma unroll
        for (int jj = 0; jj < 4; ++jj) { float b = sm.bin[j0 + jj]; u[jj] = b; u[4 + jj] = b; }
        #pragma unroll
        for (int k = 0; k < NXF; ++k) {
            float2 xv = *(const float2*)&sm.xb[buf][k][m0];
            float4 w  = *(const float4*)&sm.Win[k][j0];
            u[0] += xv.x * w.x; u[1] += xv.x * w.y; u[2] += xv.x * w.z; u[3] += xv.x * w.w;
            u[4] += xv.y * w.x; u[5] += xv.y * w.y; u[6] += xv.y * w.z; u[7] += xv.y * w.w;
        }
        #pragma unroll
        for (int jj = 0; jj < 4; ++jj) {
            float2 uv = make_float2(fmaxf(u[jj], 0.f), fmaxf(u[4 + jj], 0.f));
            *(float2*)&sm.Us[j0 + jj][m0] = uv;   // transposed store
        }

        // ---- G_r = s_r(old) @ W_hh, r = 1..3, K = 64 (dominant GEMMs) ----
        float g1[8], g2[8], g3[8];
        #pragma unroll
        for (int i = 0; i < 8; ++i) { g1[i] = 0.f; g2[i] = 0.f; g3[i] = 0.f; }
        #pragma unroll 8
        for (int k = 0; k < HID; ++k) {
            float2 h1 = *(const float2*)&sm.s1[k][m0];
            float2 h2 = *(const float2*)&sm.s2[k][m0];
            float2 h3 = *(const float2*)&sm.s3[k][m0];
            float4 w  = *(const float4*)&sm.Whh[k][j0];
            g1[0] += h1.x * w.x; g1[1] += h1.x * w.y; g1[2] += h1.x * w.z; g1[3] += h1.x * w.w;
            g1[4] += h1.y * w.x; g1[5] += h1.y * w.y; g1[6] += h1.y * w.z; g1[7] += h1.y * w.w;
            g2[0] += h2.x * w.x; g2[1] += h2.x * w.y; g2[2] += h2.x * w.z; g2[3] += h2.x * w.w;
            g2[4] += h2.y * w.x; g2[5] += h2.y * w.y; g2[6] += h2.y * w.z; g2[7] += h2.y * w.w;
            g3[0] += h3.x * w.x; g3[1] += h3.x * w.y; g3[2] += h3.x * w.z; g3[3] += h3.x * w.w;
            g3[4] += h3.y * w.x; g3[5] += h3.y * w.y; g3[6] += h3.y * w.z; g3[7] += h3.y * w.w;
        }

        // stash next x tile into alternate buffer
        if (haveNext) {
            int l0 = tid, l1 = tid + NTHR;
            sm.xb[buf ^ 1][l0 & 15][l0 >> 4] = pf0;
            sm.xb[buf ^ 1][l1 & 15][l1 >> 4] = pf1;
        }
        __syncthreads();   // sync1: Us visible; all old-state reads complete

        // ---- A = U @ W_xh + b_h, K = 64 ----
        float A[8];
        #pragma unroll
        for (int jj = 0; jj < 4; ++jj) { float b = sm.bh[j0 + jj]; A[jj] = b; A[4 + jj] = b; }
        #pragma unroll 8
        for (int k = 0; k < HID; ++k) {
            float2 uv = *(const float2*)&sm.Us[k][m0];
            float4 w  = *(const float4*)&sm.Wxh[k][j0];
            A[0] += uv.x * w.x; A[1] += uv.x * w.y; A[2] += uv.x * w.z; A[3] += uv.x * w.w;
            A[4] += uv.y * w.x; A[5] += uv.y * w.y; A[6] += uv.y * w.z; A[7] += uv.y * w.w;
        }

        // ---- tanh stage updates (write new states) + y partials ----
        float s4[8];
        #pragma unroll
        for (int jj = 0; jj < 4; ++jj) {
            float a0 = A[jj], a1 = A[4 + jj];
            *(float2*)&sm.s1[j0 + jj][m0] =
                make_float2(fast_tanh(a0), fast_tanh(a1));
            *(float2*)&sm.s2[j0 + jj][m0] =
                make_float2(fast_tanh(a0 + g1[jj]), fast_tanh(a1 + g1[4 + jj]));
            *(float2*)&sm.s3[j0 + jj][m0] =
                make_float2(fast_tanh(a0 + g2[jj]), fast_tanh(a1 + g2[4 + jj]));
            s4[jj]     = fast_tanh(a0 + g3[jj]);
            s4[4 + jj] = fast_tanh(a1 + g3[4 + jj]);
        }
        float p0 = 0.f, p1 = 0.f;
        #pragma unroll
        for (int jj = 0; jj < 4; ++jj) {
            float w = sm.Wout[j0 + jj];
            p0 += s4[jj] * w;
            p1 += s4[4 + jj] * w;
        }
        *(float2*)&sm.part[jg][m0] = make_float2(p0, p1);
        __syncthreads();   // sync2: partials + new states visible

        // ---- emit out[t+1] ----
        if (t >= emit_lo && tid < NG) {
            float y = bout;
            #pragma unroll
            for (int g = 0; g < 16; ++g) y += sm.part[g][tid];
            out[(t + 1) * NGRID + cell0 + tid] = y;
        }
    }
}

extern "C" __global__ void narx_zero_head(float* __restrict__ out) {
    int i = blockIdx.x * blockDim.x + threadIdx.x;
    if (i < DLY * NGRID) out[i] = 0.f;
}

extern "C" void kernel_launch(void* const* d_in, const int* in_sizes, int n_in,
                              void* d_out, int out_size) {
    const float* x     = (const float*)d_in[0];
    const float* W_in  = (const float*)d_in[1];
    const float* b_in  = (const float*)d_in[2];
    const float* W_xh  = (const float*)d_in[3];
    const float* W_hh  = (const float*)d_in[4];
    const float* b_h   = (const float*)d_in[5];
    const float* W_out = (const float*)d_in[6];
    const float* b_out = (const float*)d_in[7];
    float* out = (float*)d_out;

    cudaFuncSetAttribute(narx_stream_kernel,
                         cudaFuncAttributeMaxDynamicSharedMemorySize,
                         (int)sizeof(SmemLayout));

    narx_zero_head<<<(DLY * NGRID + 255) / 256, 256>>>(out);

    dim3 grid(NGRID / NG, TCH);
    narx_stream_kernel<<<grid, NTHR, sizeof(SmemLayout)>>>(
        x, W_in, b_in, W_xh, W_hh, b_h, W_out, b_out, out);
}

// round 6
// speedup vs baseline: 1.2612x; 1.2612x over previous
#include <cuda_runtime.h>
#include <math.h>

#define NT    512
#define NGRID 2048
#define NXF   16
#define HID   64
#define DLY   4
#define NG    64     // grid cells per block
#define NTHR  256
#define TCH   9      // time chunks: 32 x 9 = 288 blocks <= 296 resident slots
#define CH    57     // emission steps per chunk (9*57 = 513 >= 511)
#define XPAD  68     // padded x-tile row (reduces transposed-store conflicts)

struct __align__(16) SmemLayout {
    float Win[NXF][HID];    // W_in[k][j]  (broadcast loads -> no pad needed)
    float Wxh[HID][HID];
    float Whh[HID][HID];
    float bin[HID];
    float bh[HID];
    float Wout[HID];
    float s1[HID][NG];      // states, transposed [hidden][cell]
    float s2[HID][NG];
    float s3[HID][NG];
    float Us[HID][NG];      // relu(U) transposed [hidden][cell]
    float xb[NXF][XPAD];    // x tile transposed [feat][cell] (single buffer)
    float part[16][NG];     // y partial sums per j-group
};

__device__ __forceinline__ float fast_tanh(float v) {
    // tanh(x) = 1 - 2/(1+exp(2x)); exact identity, only MUFU rounding (~1e-6).
    float e = __expf(2.0f * v);
    return 1.0f - __fdividef(2.0f, e + 1.0f);
}

// acc[cc*4+jj] += h.cc * w.jj  (4 cells x 4 hidden outputs = 16 FMA)
#define TILE_FMA(acc, h, w) do { \
    acc[ 0] += (h).x*(w).x; acc[ 1] += (h).x*(w).y; acc[ 2] += (h).x*(w).z; acc[ 3] += (h).x*(w).w; \
    acc[ 4] += (h).y*(w).x; acc[ 5] += (h).y*(w).y; acc[ 6] += (h).y*(w).z; acc[ 7] += (h).y*(w).w; \
    acc[ 8] += (h).z*(w).x; acc[ 9] += (h).z*(w).y; acc[10] += (h).z*(w).z; acc[11] += (h).z*(w).w; \
    acc[12] += (h).w*(w).x; acc[13] += (h).w*(w).y; acc[14] += (h).w*(w).z; acc[15] += (h).w*(w).w; \
} while (0)

extern "C" __global__ void __launch_bounds__(NTHR, 2)
narx_stream_kernel(const float* __restrict__ x,
                   const float* __restrict__ W_in,
                   const float* __restrict__ b_in,
                   const float* __restrict__ W_xh,
                   const float* __restrict__ W_hh,
                   const float* __restrict__ b_h,
                   const float* __restrict__ W_out,
                   const float* __restrict__ b_out,
                   float* __restrict__ out)
{
    extern __shared__ __align__(16) char smraw[];
    SmemLayout& sm = *reinterpret_cast<SmemLayout*>(smraw);

    const int tid = threadIdx.x;
    const int mg  = tid & 15;        // 16 m-groups of 4 cells
    const int jg  = tid >> 4;        // 16 j-groups of 4 hidden
    const int m0  = mg << 2;
    const int j0  = jg << 2;
    const int cx  = tid >> 2;        // cell for x-tile transpose
    const int f0  = (tid & 3) << 2;  // first feature for x-tile transpose
    const int cell0 = blockIdx.x * NG;
    const int tb  = blockIdx.y * CH;          // first emitted t of this chunk
    const int te  = min(tb + CH, NT - 1);     // one past last emitted t
    const int ts  = max(tb - (DLY - 1), 0);   // 3-step warm-up halo
    const int emit_lo = max(tb, DLY - 1);     // t >= 3

    // ---- load weights / biases into shared ----
    for (int i = tid; i < NXF * HID; i += NTHR) sm.Win[i >> 6][i & 63] = W_in[i];
    for (int i = tid; i < HID * HID; i += NTHR) sm.Wxh[i >> 6][i & 63] = W_xh[i];
    for (int i = tid; i < HID * HID; i += NTHR) sm.Whh[i >> 6][i & 63] = W_hh[i];
    if (tid < HID) {
        sm.bin[tid]  = b_in[tid];
        sm.bh[tid]   = b_h[tid];
        sm.Wout[tid] = W_out[tid];
    }
    for (int i = tid; i < HID * NG; i += NTHR) {
        int k = i >> 6, m = i & 63;
        sm.s1[k][m] = 0.f; sm.s2[k][m] = 0.f; sm.s3[k][m] = 0.f;
    }
    const float bout = b_out[0];

    // ---- preload x[ts] tile (NG*NXF = 1024 floats), transposed ----
    {
        float4 v = *(const float4*)(x + ((size_t)ts * NGRID + cell0) * NXF + tid * 4);
        sm.xb[f0 + 0][cx] = v.x; sm.xb[f0 + 1][cx] = v.y;
        sm.xb[f0 + 2][cx] = v.z; sm.xb[f0 + 3][cx] = v.w;
    }
    __syncthreads();

    for (int t = ts; t < te; ++t) {
        // prefetch next x row into registers (STS between sync1 and sync2)
        float4 pf = make_float4(0.f, 0.f, 0.f, 0.f);
        const bool haveNext = (t + 1 < te);
        if (haveNext)
            pf = *(const float4*)(x + ((size_t)(t + 1) * NGRID + cell0) * NXF + tid * 4);

        // ---- U = relu(x[t] @ W_in + b_in), K = 16 ----
        float u[16];
        #pragma unroll
        for (int jj = 0; jj < 4; ++jj) {
            float b = sm.bin[j0 + jj];
            u[jj] = b; u[4 + jj] = b; u[8 + jj] = b; u[12 + jj] = b;
        }
        #pragma unroll
        for (int k = 0; k < NXF; ++k) {
            float4 h = *(const float4*)&sm.xb[k][m0];
            float4 w = *(const float4*)&sm.Win[k][j0];
            TILE_FMA(u, h, w);
        }
        #pragma unroll
        for (int jj = 0; jj < 4; ++jj) {
            float4 v = make_float4(fmaxf(u[jj], 0.f),      fmaxf(u[4 + jj], 0.f),
                                   fmaxf(u[8 + jj], 0.f),  fmaxf(u[12 + jj], 0.f));
            *(float4*)&sm.Us[j0 + jj][m0] = v;   // transposed store
        }

        // ---- G_r = s_r(old) @ W_hh, r = 1..3, K = 64 (dominant GEMMs) ----
        float g1[16], g2[16], g3[16];
        #pragma unroll
        for (int i = 0; i < 16; ++i) { g1[i] = 0.f; g2[i] = 0.f; g3[i] = 0.f; }
        #pragma unroll 8
        for (int k = 0; k < HID; ++k) {
            float4 h1 = *(const float4*)&sm.s1[k][m0];
            float4 h2 = *(const float4*)&sm.s2[k][m0];
            float4 h3 = *(const float4*)&sm.s3[k][m0];
            float4 w  = *(const float4*)&sm.Whh[k][j0];
            TILE_FMA(g1, h1, w);
            TILE_FMA(g2, h2, w);
            TILE_FMA(g3, h3, w);
        }
        __syncthreads();   // sync1: Us visible; all old-state + xb reads complete

        // stash next x tile (readers are past sync1; next read is after sync2)
        if (haveNext) {
            sm.xb[f0 + 0][cx] = pf.x; sm.xb[f0 + 1][cx] = pf.y;
            sm.xb[f0 + 2][cx] = pf.z; sm.xb[f0 + 3][cx] = pf.w;
        }

        // ---- A = U @ W_xh + b_h, K = 64 ----
        float A[16];
        #pragma unroll
        for (int jj = 0; jj < 4; ++jj) {
            float b = sm.bh[j0 + jj];
            A[jj] = b; A[4 + jj] = b; A[8 + jj] = b; A[12 + jj] = b;
        }
        #pragma unroll 8
        for (int k = 0; k < HID; ++k) {
            float4 h = *(const float4*)&sm.Us[k][m0];
            float4 w = *(const float4*)&sm.Wxh[k][j0];
            TILE_FMA(A, h, w);
        }

        // ---- tanh stage updates (write new states) + y partials ----
        float p0 = 0.f, p1 = 0.f, p2 = 0.f, p3 = 0.f;
        #pragma unroll
        for (int jj = 0; jj < 4; ++jj) {
            float wo = sm.Wout[j0 + jj];
            float a0 = A[jj], a1 = A[4 + jj], a2 = A[8 + jj], a3 = A[12 + jj];
            float4 v1 = make_float4(fast_tanh(a0), fast_tanh(a1),
                                    fast_tanh(a2), fast_tanh(a3));
            float4 v2 = make_float4(fast_tanh(a0 + g1[jj]),     fast_tanh(a1 + g1[4 + jj]),
                                    fast_tanh(a2 + g1[8 + jj]), fast_tanh(a3 + g1[12 + jj]));
            float4 v3 = make_float4(fast_tanh(a0 + g2[jj]),     fast_tanh(a1 + g2[4 + jj]),
                                    fast_tanh(a2 + g2[8 + jj]), fast_tanh(a3 + g2[12 + jj]));
            *(float4*)&sm.s1[j0 + jj][m0] = v1;
            *(float4*)&sm.s2[j0 + jj][m0] = v2;
            *(float4*)&sm.s3[j0 + jj][m0] = v3;
            p0 += fast_tanh(a0 + g3[jj])      * wo;
            p1 += fast_tanh(a1 + g3[4 + jj])  * wo;
            p2 += fast_tanh(a2 + g3[8 + jj])  * wo;
            p3 += fast_tanh(a3 + g3[12 + jj]) * wo;
        }
        *(float4*)&sm.part[jg][m0] = make_float4(p0, p1, p2, p3);
        __syncthreads();   // sync2: partials + new states + new xb visible

        // ---- emit out[t+1] ----
        if (t >= emit_lo && tid < NG) {
            float y = bout;
            #pragma unroll
            for (int g = 0; g < 16; ++g) y += sm.part[g][tid];
            out[(size_t)(t + 1) * NGRID + cell0 + tid] = y;
        }
    }
}

extern "C" __global__ void narx_zero_head(float* __restrict__ out) {
    int i = blockIdx.x * blockDim.x + threadIdx.x;
    if (i < DLY * NGRID) out[i] = 0.f;
}

extern "C" void kernel_launch(void* const* d_in, const int* in_sizes, int n_in,
                              void* d_out, int out_size) {
    const float* x     = (const float*)d_in[0];
    const float* W_in  = (const float*)d_in[1];
    const float* b_in  = (const float*)d_in[2];
    const float* W_xh  = (const float*)d_in[3];
    const float* W_hh  = (const float*)d_in[4];
    const float* b_h   = (const float*)d_in[5];
    const float* W_out = (const float*)d_in[6];
    const float* b_out = (const float*)d_in[7];
    float* out = (float*)d_out;

    cudaFuncSetAttribute(narx_stream_kernel,
                         cudaFuncAttributeMaxDynamicSharedMemorySize,
                         (int)sizeof(SmemLayout));

    narx_zero_head<<<(DLY * NGRID + 255) / 256, 256>>>(out);

    dim3 grid(NGRID / NG, TCH);
    narx_stream_kernel<<<grid, NTHR, sizeof(SmemLayout)>>>(
        x, W_in, b_in, W_xh, W_hh, b_h, W_out, b_out, out);
}

// round 8
// speedup vs baseline: 1.9546x; 1.5498x over previous
#include <cuda_runtime.h>
#include <cuda_bf16.h>
#include <cstdint>

#define NT    512
#define NGRID 2048
#define NXF   16
#define HID   64
#define DLY   4
#define NG    128
#define NTHR  256
#define TCH   9
#define CH    57

#define RS    144            // padded row stride (72 bf16) for all operand tiles
#define TILE  (128 * RS)     // 18432 B

#define SM_UH    0
#define SM_UL    (SM_UH + TILE)
#define SM_S1H   (SM_UL + TILE)
#define SM_S1L   (SM_S1H + TILE)
#define SM_S2H   (SM_S1L + TILE)
#define SM_S2L   (SM_S2H + TILE)
#define SM_S3H   (SM_S2L + TILE)
#define SM_S3L   (SM_S3H + TILE)
#define WT       (64 * RS)   // 9216 B
#define SM_WXH_H (SM_S3L + TILE)
#define SM_WXH_L (SM_WXH_H + WT)
#define SM_WHH_H (SM_WXH_L + WT)
#define SM_WHH_L (SM_WHH_H + WT)
#define SM_WIN   (SM_WHH_L + WT)       // fp32 [16][64]
#define SM_BIN   (SM_WIN + 4096)
#define SM_BH    (SM_BIN + 256)
#define SM_WOUT  (SM_BH + 256)
#define SM_TOTAL (SM_WOUT + 256)       // 189184 B

__device__ __forceinline__ uint32_t smem_u32(const void* p) {
    uint32_t a;
    asm("{ .reg .u64 t; cvta.to.shared.u64 t, %1; cvt.u32.u64 %0, t; }" : "=r"(a) : "l"(p));
    return a;
}

#define LDSM4(r, addr) \
    asm volatile("ldmatrix.sync.aligned.m8n8.x4.shared.b16 {%0,%1,%2,%3}, [%4];" \
        : "=r"((r)[0]), "=r"((r)[1]), "=r"((r)[2]), "=r"((r)[3]) : "r"(addr) : "memory")
#define LDSM4T(r, addr) \
    asm volatile("ldmatrix.sync.aligned.m8n8.x4.trans.shared.b16 {%0,%1,%2,%3}, [%4];" \
        : "=r"((r)[0]), "=r"((r)[1]), "=r"((r)[2]), "=r"((r)[3]) : "r"(addr) : "memory")
#define MMA4(d, a, b0_, b1_) \
    asm volatile("mma.sync.aligned.m16n8k16.row.col.f32.bf16.bf16.f32 " \
        "{%0,%1,%2,%3}, {%4,%5,%6,%7}, {%8,%9}, {%0,%1,%2,%3};" \
        : "+f"((d)[0]), "+f"((d)[1]), "+f"((d)[2]), "+f"((d)[3]) \
        : "r"((a)[0]), "r"((a)[1]), "r"((a)[2]), "r"((a)[3]), "r"(b0_), "r"(b1_))

__device__ __forceinline__ float fast_tanh(float v) {
    float e = __expf(2.0f * v);
    return 1.0f - __fdividef(2.0f, e + 1.0f);
}
__device__ __forceinline__ void split_pack(float a, float b, uint32_t& hi, uint32_t& lo) {
    __nv_bfloat16 ha = __float2bfloat16(a), hb = __float2bfloat16(b);
    float ra = a - __bfloat162float(ha), rb = b - __bfloat162float(hb);
    __nv_bfloat162 H; H.x = ha; H.y = hb;
    __nv_bfloat162 L; L.x = __float2bfloat16(ra); L.y = __float2bfloat16(rb);
    hi = *(uint32_t*)&H;
    lo = *(uint32_t*)&L;
}

// compute U = relu(x @ W_in + b_in) for one (cell, 32-j half) and store hi/lo bf16
__device__ __forceinline__ void u_compute_store(const float xk[NXF], char* smp,
                                                int cell, int j0) {
    const float* Win = (const float*)(smp + SM_WIN);
    const float* bin = (const float*)(smp + SM_BIN);
    float u[32];
    #pragma unroll
    for (int jj = 0; jj < 32; ++jj) u[jj] = bin[j0 + jj];
    #pragma unroll
    for (int k = 0; k < NXF; ++k) {
        float xv = xk[k];
        #pragma unroll
        for (int jb = 0; jb < 8; ++jb) {
            float4 w = *(const float4*)&Win[k * HID + j0 + jb * 4];
            u[jb*4+0] += xv * w.x; u[jb*4+1] += xv * w.y;
            u[jb*4+2] += xv * w.z; u[jb*4+3] += xv * w.w;
        }
    }
    char* rowH = smp + SM_UH + cell * RS;
    char* rowL = smp + SM_UL + cell * RS;
    #pragma unroll
    for (int jj = 0; jj < 16; ++jj) {
        uint32_t hi, lo;
        split_pack(fmaxf(u[2*jj], 0.f), fmaxf(u[2*jj+1], 0.f), hi, lo);
        *(uint32_t*)(rowH + (j0 + 2*jj) * 2) = hi;
        *(uint32_t*)(rowL + (j0 + 2*jj) * 2) = lo;
    }
}

__device__ __forceinline__ void st_state(char* baseH, char* baseL, int rowR, int rowR8,
                                         int colB, float v0, float v1, float v2, float v3) {
    uint32_t h01, l01, h23, l23;
    split_pack(v0, v1, h01, l01);
    split_pack(v2, v3, h23, l23);
    *(uint32_t*)(baseH + rowR  + colB) = h01;
    *(uint32_t*)(baseH + rowR8 + colB) = h23;
    *(uint32_t*)(baseL + rowR  + colB) = l01;
    *(uint32_t*)(baseL + rowR8 + colB) = l23;
}

extern "C" __global__ void __launch_bounds__(NTHR, 1)
narx_mma_kernel(const float* __restrict__ x,
                const float* __restrict__ W_in,  const float* __restrict__ b_in,
                const float* __restrict__ W_xh,  const float* __restrict__ W_hh,
                const float* __restrict__ b_h,   const float* __restrict__ W_out,
                const float* __restrict__ b_out, float* __restrict__ out)
{
    extern __shared__ __align__(16) char smp[];
    const uint32_t sb = smem_u32(smp);
    const int tid = threadIdx.x, wid = tid >> 5, lane = tid & 31;
    const int m0 = wid * 16;                 // warp's 16 cells
    const int cell0 = blockIdx.x * NG;
    const int tb = blockIdx.y * CH;
    const int te = min(tb + CH, NT - 1);
    const int ts = max(tb - (DLY - 1), 0);
    const int emit_lo = max(tb, DLY - 1);

    // ---- prologue: weights ----
    for (int i = tid; i < HID * HID; i += NTHR) {
        int k = i >> 6, n = i & 63;
        float w1 = W_xh[i];
        __nv_bfloat16 h1 = __float2bfloat16(w1);
        ((__nv_bfloat16*)(smp + SM_WXH_H))[k*72 + n] = h1;
        ((__nv_bfloat16*)(smp + SM_WXH_L))[k*72 + n] = __float2bfloat16(w1 - __bfloat162float(h1));
        float w2 = W_hh[i];
        __nv_bfloat16 h2 = __float2bfloat16(w2);
        ((__nv_bfloat16*)(smp + SM_WHH_H))[k*72 + n] = h2;
        ((__nv_bfloat16*)(smp + SM_WHH_L))[k*72 + n] = __float2bfloat16(w2 - __bfloat162float(h2));
    }
    for (int i = tid; i < NXF * HID; i += NTHR) ((float*)(smp + SM_WIN))[i] = W_in[i];
    if (tid < HID) {
        ((float*)(smp + SM_BIN))[tid]  = b_in[tid];
        ((float*)(smp + SM_BH))[tid]   = b_h[tid];
        ((float*)(smp + SM_WOUT))[tid] = W_out[tid];
    }
    // zero S1..S3 hi/lo tiles (contiguous 6*TILE bytes)
    for (int i = tid; i < 6 * TILE / 16; i += NTHR)
        ((uint4*)(smp + SM_S1H))[i] = make_uint4(0, 0, 0, 0);
    const float bout = b_out[0];
    __syncthreads();

    // ---- U(ts) ----
    const int ucell = tid >> 1, uj0 = (tid & 1) * 32;
    {
        float xk[NXF];
        const float* xr = x + ((size_t)ts * NGRID + cell0 + ucell) * NXF;
        #pragma unroll
        for (int q = 0; q < 4; ++q) {
            float4 v = *(const float4*)(xr + q * 4);
            xk[q*4] = v.x; xk[q*4+1] = v.y; xk[q*4+2] = v.z; xk[q*4+3] = v.w;
        }
        u_compute_store(xk, smp, ucell, uj0);
    }
    __syncthreads();

    // per-thread ldmatrix lane offsets
    const uint32_t aOff = (uint32_t)((lane & 15) * RS + (lane >> 4) * 16);
    const uint32_t bOff = (uint32_t)(((lane & 7) + ((lane >> 3) & 1) * 8) * RS + (lane >> 4) * 16);
    const uint32_t uhA  = sb + SM_UH  + m0 * RS + aOff;
    const uint32_t ulA  = sb + SM_UL  + m0 * RS + aOff;
    const uint32_t s1hA = sb + SM_S1H + m0 * RS + aOff;
    const uint32_t s1lA = sb + SM_S1L + m0 * RS + aOff;
    const uint32_t s2hA = sb + SM_S2H + m0 * RS + aOff;
    const uint32_t s2lA = sb + SM_S2L + m0 * RS + aOff;
    const uint32_t s3hA = sb + SM_S3H + m0 * RS + aOff;
    const uint32_t s3lA = sb + SM_S3L + m0 * RS + aOff;
    const uint32_t wxhhB = sb + SM_WXH_H + bOff;
    const uint32_t wxhlB = sb + SM_WXH_L + bOff;
    const uint32_t whhhB = sb + SM_WHH_H + bOff;
    const uint32_t whhlB = sb + SM_WHH_L + bOff;

    const float* bhp  = (const float*)(smp + SM_BH);
    const float* wop  = (const float*)(smp + SM_WOUT);
    const int r    = lane >> 2;
    const int rowR  = (m0 + r) * RS;
    const int rowR8 = (m0 + r + 8) * RS;

    for (int t = ts; t < te; ++t) {
        const bool haveNext = (t + 1 < te);
        float xk[NXF];
        if (haveNext) {
            const float* xr = x + ((size_t)(t + 1) * NGRID + cell0 + ucell) * NXF;
            #pragma unroll
            for (int q = 0; q < 4; ++q) {
                float4 v = *(const float4*)(xr + q * 4);
                xk[q*4] = v.x; xk[q*4+1] = v.y; xk[q*4+2] = v.z; xk[q*4+3] = v.w;
            }
        }

        // ---- D0 = U @ Wxh  (3-term bf16 split) ----
        float aU[32];
        #pragma unroll
        for (int i = 0; i < 32; ++i) aU[i] = 0.f;
        for (int kt = 0; kt < 4; ++kt) {
            uint32_t a1[4], a2[4];
            LDSM4(a1, uhA + kt * 32);
            LDSM4(a2, ulA + kt * 32);
            #pragma unroll
            for (int ntp = 0; ntp < 4; ++ntp) {
                uint32_t b4[4];
                LDSM4T(b4, wxhhB + kt * (16 * RS) + ntp * 32);
                MMA4(&aU[ntp*8],     a1, b4[0], b4[1]); MMA4(&aU[ntp*8 + 4], a1, b4[2], b4[3]);
                MMA4(&aU[ntp*8],     a2, b4[0], b4[1]); MMA4(&aU[ntp*8 + 4], a2, b4[2], b4[3]);
            }
        }
        for (int kt = 0; kt < 4; ++kt) {
            uint32_t a1[4];
            LDSM4(a1, uhA + kt * 32);
            #pragma unroll
            for (int ntp = 0; ntp < 4; ++ntp) {
                uint32_t b4[4];
                LDSM4T(b4, wxhlB + kt * (16 * RS) + ntp * 32);
                MMA4(&aU[ntp*8],     a1, b4[0], b4[1]); MMA4(&aU[ntp*8 + 4], a1, b4[2], b4[3]);
            }
        }

        // ---- G_r = S_r @ Whh, r = 1..3 (3-term each) ----
        float aS[96];
        #pragma unroll
        for (int i = 0; i < 96; ++i) aS[i] = 0.f;
        for (int kt = 0; kt < 4; ++kt) {
            uint32_t ah0[4], al0[4], ah1[4], al1[4], ah2[4], al2[4];
            LDSM4(ah0, s1hA + kt * 32); LDSM4(al0, s1lA + kt * 32);
            LDSM4(ah1, s2hA + kt * 32); LDSM4(al1, s2lA + kt * 32);
            LDSM4(ah2, s3hA + kt * 32); LDSM4(al2, s3lA + kt * 32);
            #pragma unroll
            for (int ntp = 0; ntp < 4; ++ntp) {
                uint32_t b4[4];
                LDSM4T(b4, whhhB + kt * (16 * RS) + ntp * 32);
                MMA4(&aS[     ntp*8], ah0, b4[0], b4[1]); MMA4(&aS[     ntp*8+4], ah0, b4[2], b4[3]);
                MMA4(&aS[     ntp*8], al0, b4[0], b4[1]); MMA4(&aS[     ntp*8+4], al0, b4[2], b4[3]);
                MMA4(&aS[32 + ntp*8], ah1, b4[0], b4[1]); MMA4(&aS[32 + ntp*8+4], ah1, b4[2], b4[3]);
                MMA4(&aS[32 + ntp*8], al1, b4[0], b4[1]); MMA4(&aS[32 + ntp*8+4], al1, b4[2], b4[3]);
                MMA4(&aS[64 + ntp*8], ah2, b4[0], b4[1]); MMA4(&aS[64 + ntp*8+4], ah2, b4[2], b4[3]);
                MMA4(&aS[64 + ntp*8], al2, b4[0], b4[1]); MMA4(&aS[64 + ntp*8+4], al2, b4[2], b4[3]);
                uint32_t c4[4];
                LDSM4T(c4, whhlB + kt * (16 * RS) + ntp * 32);
                MMA4(&aS[     ntp*8], ah0, c4[0], c4[1]); MMA4(&aS[     ntp*8+4], ah0, c4[2], c4[3]);
                MMA4(&aS[32 + ntp*8], ah1, c4[0], c4[1]); MMA4(&aS[32 + ntp*8+4], ah1, c4[2], c4[3]);
                MMA4(&aS[64 + ntp*8], ah2, c4[0], c4[1]); MMA4(&aS[64 + ntp*8+4], ah2, c4[2], c4[3]);
            }
        }

        __syncthreads();   // all warps done reading U tile (ldmatrix complete)

        // ---- U(t+1) ----
        if (haveNext) u_compute_store(xk, smp, ucell, uj0);

        // ---- epilogue: tanh stages, state stores (warp-private rows), y ----
        float pr = 0.f, pr8 = 0.f;
        #pragma unroll
        for (int nt = 0; nt < 8; ++nt) {
            const int col = nt * 8 + 2 * (lane & 3);
            const int colB = col * 2;
            float2 b2 = *(const float2*)&bhp[col];
            float A0 = aU[nt*4+0] + b2.x, A1 = aU[nt*4+1] + b2.y;
            float A2 = aU[nt*4+2] + b2.x, A3 = aU[nt*4+3] + b2.y;
            st_state(smp + SM_S1H, smp + SM_S1L, rowR, rowR8, colB,
                     fast_tanh(A0), fast_tanh(A1), fast_tanh(A2), fast_tanh(A3));
            st_state(smp + SM_S2H, smp + SM_S2L, rowR, rowR8, colB,
                     fast_tanh(A0 + aS[nt*4+0]), fast_tanh(A1 + aS[nt*4+1]),
                     fast_tanh(A2 + aS[nt*4+2]), fast_tanh(A3 + aS[nt*4+3]));
            st_state(smp + SM_S3H, smp + SM_S3L, rowR, rowR8, colB,
                     fast_tanh(A0 + aS[32+nt*4+0]), fast_tanh(A1 + aS[32+nt*4+1]),
                     fast_tanh(A2 + aS[32+nt*4+2]), fast_tanh(A3 + aS[32+nt*4+3]));
            float2 w2 = *(const float2*)&wop[col];
            pr  += fast_tanh(A0 + aS[64+nt*4+0]) * w2.x + fast_tanh(A1 + aS[64+nt*4+1]) * w2.y;
            pr8 += fast_tanh(A2 + aS[64+nt*4+2]) * w2.x + fast_tanh(A3 + aS[64+nt*4+3]) * w2.y;
        }
        pr  += __shfl_xor_sync(0xffffffffu, pr, 1);
        pr  += __shfl_xor_sync(0xffffffffu, pr, 2);
        pr8 += __shfl_xor_sync(0xffffffffu, pr8, 1);
        pr8 += __shfl_xor_sync(0xffffffffu, pr8, 2);
        if ((lane & 3) == 0 && t >= emit_lo) {
            size_t base = (size_t)(t + 1) * NGRID + cell0 + m0;
            out[base + r]     = pr + bout;
            out[base + r + 8] = pr8 + bout;
        }

        __syncthreads();   // U(t+1) + new states visible before next step
    }
}

extern "C" __global__ void narx_zero_head(float* __restrict__ out) {
    int i = blockIdx.x * blockDim.x + threadIdx.x;
    if (i < DLY * NGRID) out[i] = 0.f;
}

extern "C" void kernel_launch(void* const* d_in, const int* in_sizes, int n_in,
                              void* d_out, int out_size) {
    const float* x     = (const float*)d_in[0];
    const float* W_in  = (const float*)d_in[1];
    const float* b_in  = (const float*)d_in[2];
    const float* W_xh  = (const float*)d_in[3];
    const float* W_hh  = (const float*)d_in[4];
    const float* b_h   = (const float*)d_in[5];
    const float* W_out = (const float*)d_in[6];
    const float* b_out = (const float*)d_in[7];
    float* out = (float*)d_out;

    cudaFuncSetAttribute(narx_mma_kernel,
                         cudaFuncAttributeMaxDynamicSharedMemorySize, SM_TOTAL);

    narx_zero_head<<<(DLY * NGRID + 255) / 256, 256>>>(out);

    dim3 grid(NGRID / NG, TCH);
    narx_mma_kernel<<<grid, NTHR, SM_TOTAL>>>(
        x, W_in, b_in, W_xh, W_hh, b_h, W_out, b_out, out);
}

// round 9
// speedup vs baseline: 2.8497x; 1.4580x over previous
#include <cuda_runtime.h>
#include <cuda_bf16.h>
#include <cstdint>

#define NT    512
#define NGRID 2048
#define NXF   16
#define HID   64
#define DLY   4
#define NG    128
#define NTHR  256
#define TCH   9
#define CH    57
#define RS    144        // weight tile row stride (72 bf16)

#define WT    (64 * RS)  // 9216 B per 64x64 weight tile
#define WIT   (16 * RS)  // 2304 B per 16x64 W_in tile
#define SM_WXH_H 0
#define SM_WXH_L (WT)
#define SM_WHH_H (2 * WT)
#define SM_WHH_L (3 * WT)
#define SM_WIN_H (4 * WT)
#define SM_WIN_L (4 * WT + WIT)
#define SM_BIN   (4 * WT + 2 * WIT)
#define SM_BH    (SM_BIN + 256)
#define SM_WOUT  (SM_BH + 256)
#define SM_TOTAL (SM_WOUT + 256)   // ~42.5 KB (static shared)

__device__ __forceinline__ uint32_t smem_u32(const void* p) {
    uint32_t a;
    asm("{ .reg .u64 t; cvta.to.shared.u64 t, %1; cvt.u32.u64 %0, t; }" : "=r"(a) : "l"(p));
    return a;
}

#define LDSM4T(r, addr) \
    asm volatile("ldmatrix.sync.aligned.m8n8.x4.trans.shared.b16 {%0,%1,%2,%3}, [%4];" \
        : "=r"((r)[0]), "=r"((r)[1]), "=r"((r)[2]), "=r"((r)[3]) : "r"(addr) : "memory")
#define MMA4(d, a, b0_, b1_) \
    asm volatile("mma.sync.aligned.m16n8k16.row.col.f32.bf16.bf16.f32 " \
        "{%0,%1,%2,%3}, {%4,%5,%6,%7}, {%8,%9}, {%0,%1,%2,%3};" \
        : "+f"((d)[0]), "+f"((d)[1]), "+f"((d)[2]), "+f"((d)[3]) \
        : "r"((a)[0]), "r"((a)[1]), "r"((a)[2]), "r"((a)[3]), "r"(b0_), "r"(b1_))

__device__ __forceinline__ float fast_tanh(float v) {
    float e = __expf(2.0f * v);
    return 1.0f - __fdividef(2.0f, e + 1.0f);
}
// hi = bf16 truncation of both floats, packed (1 PRMT)
__device__ __forceinline__ uint32_t packhi(float a, float b) {
    uint32_t r;
    asm("prmt.b32 %0, %1, %2, 0x7632;"
        : "=r"(r) : "r"(__float_as_uint(a)), "r"(__float_as_uint(b)));
    return r;
}
// lo = rn-bf16 of exact residual after truncation
__device__ __forceinline__ uint32_t packlo(float a, float b) {
    float ha = __uint_as_float(__float_as_uint(a) & 0xFFFF0000u);
    float hb = __uint_as_float(__float_as_uint(b) & 0xFFFF0000u);
    __nv_bfloat162 t = __floats2bfloat162_rn(a - ha, b - hb);
    return *(uint32_t*)&t;
}

// G += S @ Whh (3-term bf16 split), frags in registers, B via LDSM
__device__ __forceinline__ void state_gemm(float* G, const uint32_t* sh, const uint32_t* sl,
                                           uint32_t wh, uint32_t wl) {
    #pragma unroll
    for (int kt = 0; kt < 4; ++kt) {
        #pragma unroll
        for (int ntp = 0; ntp < 4; ++ntp) {
            uint32_t b4[4];
            LDSM4T(b4, wh + kt * (16 * RS) + ntp * 32);
            MMA4(&G[ntp*8],   sh + kt*4, b4[0], b4[1]); MMA4(&G[ntp*8+4], sh + kt*4, b4[2], b4[3]);
            MMA4(&G[ntp*8],   sl + kt*4, b4[0], b4[1]); MMA4(&G[ntp*8+4], sl + kt*4, b4[2], b4[3]);
            uint32_t c4[4];
            LDSM4T(c4, wl + kt * (16 * RS) + ntp * 32);
            MMA4(&G[ntp*8],   sh + kt*4, c4[0], c4[1]); MMA4(&G[ntp*8+4], sh + kt*4, c4[2], c4[3]);
        }
    }
}

// D-frag values (A+G) -> tanh -> repack as next-step A-frags (in registers)
__device__ __forceinline__ void tanh_pack(const float* A, const float* G,
                                          uint32_t* sh, uint32_t* sl) {
    #pragma unroll
    for (int j = 0; j < 8; ++j) {
        float s0 = fast_tanh(A[4*j+0] + G[4*j+0]);
        float s1 = fast_tanh(A[4*j+1] + G[4*j+1]);
        float s2 = fast_tanh(A[4*j+2] + G[4*j+2]);
        float s3 = fast_tanh(A[4*j+3] + G[4*j+3]);
        const int kt = j >> 1;
        if ((j & 1) == 0) {
            sh[kt*4+0] = packhi(s0, s1); sl[kt*4+0] = packlo(s0, s1);
            sh[kt*4+1] = packhi(s2, s3); sl[kt*4+1] = packlo(s2, s3);
        } else {
            sh[kt*4+2] = packhi(s0, s1); sl[kt*4+2] = packlo(s0, s1);
            sh[kt*4+3] = packhi(s2, s3); sl[kt*4+3] = packlo(s2, s3);
        }
    }
}
__device__ __forceinline__ void tanh_pack0(const float* A, uint32_t* sh, uint32_t* sl) {
    #pragma unroll
    for (int j = 0; j < 8; ++j) {
        float s0 = fast_tanh(A[4*j+0]);
        float s1 = fast_tanh(A[4*j+1]);
        float s2 = fast_tanh(A[4*j+2]);
        float s3 = fast_tanh(A[4*j+3]);
        const int kt = j >> 1;
        if ((j & 1) == 0) {
            sh[kt*4+0] = packhi(s0, s1); sl[kt*4+0] = packlo(s0, s1);
            sh[kt*4+1] = packhi(s2, s3); sl[kt*4+1] = packlo(s2, s3);
        } else {
            sh[kt*4+2] = packhi(s0, s1); sl[kt*4+2] = packlo(s0, s1);
            sh[kt*4+3] = packhi(s2, s3); sl[kt*4+3] = packlo(s2, s3);
        }
    }
}

extern "C" __global__ void __launch_bounds__(NTHR, 1)
narx_frag_kernel(const float* __restrict__ x,
                 const float* __restrict__ W_in,  const float* __restrict__ b_in,
                 const float* __restrict__ W_xh,  const float* __restrict__ W_hh,
                 const float* __restrict__ b_h,   const float* __restrict__ W_out,
                 const float* __restrict__ b_out, float* __restrict__ out)
{
    __shared__ __align__(16) char smp[SM_TOTAL];
    const uint32_t sb = smem_u32(smp);
    const int tid = threadIdx.x, wid = tid >> 5, lane = tid & 31;
    const int gr = lane >> 2, c = lane & 3;
    const int m0 = wid * 16;
    const int cell0 = blockIdx.x * NG;
    const int tb = blockIdx.y * CH;
    const int te = min(tb + CH, NT - 1);
    const int ts = max(tb - (DLY - 1), 0);
    const int emit_lo = max(tb, DLY - 1);

    // ---- prologue: truncation-split weights into smem (hi/lo bf16) ----
    for (int i = tid; i < HID * HID; i += NTHR) {
        int k = i >> 6, n = i & 63;
        float w1 = W_xh[i];
        uint32_t h1 = __float_as_uint(w1) & 0xFFFF0000u;
        ((uint16_t*)(smp + SM_WXH_H))[k*72 + n] = (uint16_t)(h1 >> 16);
        ((__nv_bfloat16*)(smp + SM_WXH_L))[k*72 + n] = __float2bfloat16(w1 - __uint_as_float(h1));
        float w2 = W_hh[i];
        uint32_t h2 = __float_as_uint(w2) & 0xFFFF0000u;
        ((uint16_t*)(smp + SM_WHH_H))[k*72 + n] = (uint16_t)(h2 >> 16);
        ((__nv_bfloat16*)(smp + SM_WHH_L))[k*72 + n] = __float2bfloat16(w2 - __uint_as_float(h2));
    }
    for (int i = tid; i < NXF * HID; i += NTHR) {
        int k = i >> 6, n = i & 63;
        float w = W_in[i];
        uint32_t h = __float_as_uint(w) & 0xFFFF0000u;
        ((uint16_t*)(smp + SM_WIN_H))[k*72 + n] = (uint16_t)(h >> 16);
        ((__nv_bfloat16*)(smp + SM_WIN_L))[k*72 + n] = __float2bfloat16(w - __uint_as_float(h));
    }
    if (tid < HID) {
        ((float*)(smp + SM_BIN))[tid]  = b_in[tid];
        ((float*)(smp + SM_BH))[tid]   = b_h[tid];
        ((float*)(smp + SM_WOUT))[tid] = W_out[tid];
    }
    const float bout = b_out[0];
    __syncthreads();   // only barrier: weights read-only hereafter

    // per-lane LDSM B addresses
    const uint32_t bOff  = (uint32_t)(((lane & 7) + ((lane >> 3) & 1) * 8) * RS + (lane >> 4) * 16);
    const uint32_t wxh_h = sb + SM_WXH_H + bOff;
    const uint32_t wxh_l = sb + SM_WXH_L + bOff;
    const uint32_t whh_h = sb + SM_WHH_H + bOff;
    const uint32_t whh_l = sb + SM_WHH_L + bOff;
    const uint32_t win_h = sb + SM_WIN_H + bOff;
    const uint32_t win_l = sb + SM_WIN_L + bOff;

    const float* binp = (const float*)(smp + SM_BIN);
    const float* bhp  = (const float*)(smp + SM_BH);
    const float* wop  = (const float*)(smp + SM_WOUT);

    // state A-frags in registers: 3 states x (4kt x 4regs) hi+lo, start at 0
    uint32_t SH[3][16], SL[3][16];
    #pragma unroll
    for (int r = 0; r < 3; ++r)
        #pragma unroll
        for (int q = 0; q < 16; ++q) { SH[r][q] = 0u; SL[r][q] = 0u; }

    // x row pointers for this lane (rows gr, gr+8 of warp's 16 cells)
    const size_t tstride = (size_t)NGRID * NXF;
    const float* xr0 = x + ((size_t)ts * NGRID + cell0 + m0 + gr)     * NXF + 2 * c;
    const float* xr8 = x + ((size_t)ts * NGRID + cell0 + m0 + gr + 8) * NXF + 2 * c;
    float2 xn0 = *(const float2*)(xr0);
    float2 xn1 = *(const float2*)(xr0 + 8);
    float2 xn2 = *(const float2*)(xr8);
    float2 xn3 = *(const float2*)(xr8 + 8);
    xr0 += tstride; xr8 += tstride;

    for (int t = ts; t < te; ++t) {
        // ---- x A-frags (a0:(r,2c) a1:(r+8,2c) a2:(r,2c+8) a3:(r+8,2c+8)) ----
        uint32_t xh[4], xl[4];
        xh[0] = packhi(xn0.x, xn0.y); xl[0] = packlo(xn0.x, xn0.y);
        xh[1] = packhi(xn2.x, xn2.y); xl[1] = packlo(xn2.x, xn2.y);
        xh[2] = packhi(xn1.x, xn1.y); xl[2] = packlo(xn1.x, xn1.y);
        xh[3] = packhi(xn3.x, xn3.y); xl[3] = packlo(xn3.x, xn3.y);
        // prefetch next row (t+1 <= te <= NT-1: always in-bounds)
        xn0 = *(const float2*)(xr0);
        xn1 = *(const float2*)(xr0 + 8);
        xn2 = *(const float2*)(xr8);
        xn3 = *(const float2*)(xr8 + 8);
        xr0 += tstride; xr8 += tstride;

        // ---- U = relu(x @ W_in + b_in), K=16, 3-term ----
        float acc[32];
        #pragma unroll
        for (int i = 0; i < 32; ++i) acc[i] = 0.f;
        #pragma unroll
        for (int ntp = 0; ntp < 4; ++ntp) {
            uint32_t b4[4];
            LDSM4T(b4, win_h + ntp * 32);
            MMA4(&acc[ntp*8],   xh, b4[0], b4[1]); MMA4(&acc[ntp*8+4], xh, b4[2], b4[3]);
            MMA4(&acc[ntp*8],   xl, b4[0], b4[1]); MMA4(&acc[ntp*8+4], xl, b4[2], b4[3]);
            uint32_t c4[4];
            LDSM4T(c4, win_l + ntp * 32);
            MMA4(&acc[ntp*8],   xh, c4[0], c4[1]); MMA4(&acc[ntp*8+4], xh, c4[2], c4[3]);
        }
        uint32_t uh[16], ul[16];
        #pragma unroll
        for (int j = 0; j < 8; ++j) {
            float2 b2 = *(const float2*)&binp[j * 8 + 2 * c];
            float u0 = fmaxf(acc[4*j+0] + b2.x, 0.f);
            float u1 = fmaxf(acc[4*j+1] + b2.y, 0.f);
            float u2 = fmaxf(acc[4*j+2] + b2.x, 0.f);
            float u3 = fmaxf(acc[4*j+3] + b2.y, 0.f);
            const int kt = j >> 1;
            if ((j & 1) == 0) {
                uh[kt*4+0] = packhi(u0, u1); ul[kt*4+0] = packlo(u0, u1);
                uh[kt*4+1] = packhi(u2, u3); ul[kt*4+1] = packlo(u2, u3);
            } else {
                uh[kt*4+2] = packhi(u0, u1); ul[kt*4+2] = packlo(u0, u1);
                uh[kt*4+3] = packhi(u2, u3); ul[kt*4+3] = packlo(u2, u3);
            }
        }

        // ---- A = U @ Wxh + b_h, K=64, 3-term ----
        float A[32];
        #pragma unroll
        for (int i = 0; i < 32; ++i) A[i] = 0.f;
        #pragma unroll
        for (int kt = 0; kt < 4; ++kt) {
            #pragma unroll
            for (int ntp = 0; ntp < 4; ++ntp) {
                uint32_t b4[4];
                LDSM4T(b4, wxh_h + kt * (16 * RS) + ntp * 32);
                MMA4(&A[ntp*8],   &uh[kt*4], b4[0], b4[1]); MMA4(&A[ntp*8+4], &uh[kt*4], b4[2], b4[3]);
                MMA4(&A[ntp*8],   &ul[kt*4], b4[0], b4[1]); MMA4(&A[ntp*8+4], &ul[kt*4], b4[2], b4[3]);
                uint32_t c4[4];
                LDSM4T(c4, wxh_l + kt * (16 * RS) + ntp * 32);
                MMA4(&A[ntp*8],   &uh[kt*4], c4[0], c4[1]); MMA4(&A[ntp*8+4], &uh[kt*4], c4[2], c4[3]);
            }
        }
        #pragma unroll
        for (int j = 0; j < 8; ++j) {
            float2 b2 = *(const float2*)&bhp[j * 8 + 2 * c];
            A[4*j+0] += b2.x; A[4*j+1] += b2.y; A[4*j+2] += b2.x; A[4*j+3] += b2.y;
        }

        // ---- s4 = tanh(A + S3_old@Whh) -> y ----
        float p = 0.f, p8 = 0.f;
        {
            float G[32];
            #pragma unroll
            for (int i = 0; i < 32; ++i) G[i] = 0.f;
            state_gemm(G, SH[2], SL[2], whh_h, whh_l);
            #pragma unroll
            for (int j = 0; j < 8; ++j) {
                float2 w2 = *(const float2*)&wop[j * 8 + 2 * c];
                p  += fast_tanh(A[4*j+0] + G[4*j+0]) * w2.x
                    + fast_tanh(A[4*j+1] + G[4*j+1]) * w2.y;
                p8 += fast_tanh(A[4*j+2] + G[4*j+2]) * w2.x
                    + fast_tanh(A[4*j+3] + G[4*j+3]) * w2.y;
            }
        }
        // ---- S3_new = tanh(A + S2_old@Whh) ----
        {
            float G[32];
            #pragma unroll
            for (int i = 0; i < 32; ++i) G[i] = 0.f;
            state_gemm(G, SH[1], SL[1], whh_h, whh_l);
            tanh_pack(A, G, SH[2], SL[2]);
        }
        // ---- S2_new = tanh(A + S1_old@Whh) ----
        {
            float G[32];
            #pragma unroll
            for (int i = 0; i < 32; ++i) G[i] = 0.f;
            state_gemm(G, SH[0], SL[0], whh_h, whh_l);
            tanh_pack(A, G, SH[1], SL[1]);
        }
        // ---- S1_new = tanh(A) ----
        tanh_pack0(A, SH[0], SL[0]);

        // ---- emit y ----
        p  += __shfl_xor_sync(0xffffffffu, p, 1);
        p  += __shfl_xor_sync(0xffffffffu, p, 2);
        p8 += __shfl_xor_sync(0xffffffffu, p8, 1);
        p8 += __shfl_xor_sync(0xffffffffu, p8, 2);
        if (c == 0 && t >= emit_lo) {
            size_t base = (size_t)(t + 1) * NGRID + cell0 + m0;
            out[base + gr]     = p  + bout;
            out[base + gr + 8] = p8 + bout;
        }
    }
}

extern "C" __global__ void narx_zero_head(float* __restrict__ out) {
    int i = blockIdx.x * blockDim.x + threadIdx.x;
    if (i < DLY * NGRID) out[i] = 0.f;
}

extern "C" void kernel_launch(void* const* d_in, const int* in_sizes, int n_in,
                              void* d_out, int out_size) {
    const float* x     = (const float*)d_in[0];
    const float* W_in  = (const float*)d_in[1];
    const float* b_in  = (const float*)d_in[2];
    const float* W_xh  = (const float*)d_in[3];
    const float* W_hh  = (const float*)d_in[4];
    const float* b_h   = (const float*)d_in[5];
    const float* W_out = (const float*)d_in[6];
    const float* b_out = (const float*)d_in[7];
    float* out = (float*)d_out;

    narx_zero_head<<<(DLY * NGRID + 255) / 256, 256>>>(out);

    dim3 grid(NGRID / NG, TCH);
    narx_frag_kernel<<<grid, NTHR>>>(
        x, W_in, b_in, W_xh, W_hh, b_h, W_out, b_out, out);
}

// round 10
// speedup vs baseline: 3.4625x; 1.2151x over previous
#include <cuda_runtime.h>
#include <cuda_bf16.h>
#include <cstdint>

#define NT    512
#define NGRID 2048
#define NXF   16
#define HID   64
#define DLY   4
#define NG    128
#define NTHR  256
#define TCH   9
#define CH    57
#define RS    144        // weight tile row stride (72 bf16)

#define WT    (64 * RS)  // 9216 B per 64x64 weight tile
#define WIT   (16 * RS)  // 2304 B per 16x64 W_in tile
#define SM_WXH_H 0
#define SM_WXH_L (WT)
#define SM_WHH_H (2 * WT)
#define SM_WHH_L (3 * WT)
#define SM_WIN_H (4 * WT)
#define SM_WIN_L (4 * WT + WIT)
#define SM_BIN   (4 * WT + 2 * WIT)
#define SM_BH    (SM_BIN + 256)
#define SM_WOUT  (SM_BH + 256)
#define SM_TOTAL (SM_WOUT + 256)   // ~42.5 KB (static shared)

__device__ __forceinline__ uint32_t smem_u32(const void* p) {
    uint32_t a;
    asm("{ .reg .u64 t; cvta.to.shared.u64 t, %1; cvt.u32.u64 %0, t; }" : "=r"(a) : "l"(p));
    return a;
}

// NOTE: no "memory" clobber — after the prologue __syncthreads() shared memory
// is never written, so the scheduler may move these freely across MMAs.
#define LDSM4T(r, addr) \
    asm volatile("ldmatrix.sync.aligned.m8n8.x4.trans.shared.b16 {%0,%1,%2,%3}, [%4];" \
        : "=r"((r)[0]), "=r"((r)[1]), "=r"((r)[2]), "=r"((r)[3]) : "r"(addr))
#define MMA4(d, a, b0_, b1_) \
    asm volatile("mma.sync.aligned.m16n8k16.row.col.f32.bf16.bf16.f32 " \
        "{%0,%1,%2,%3}, {%4,%5,%6,%7}, {%8,%9}, {%0,%1,%2,%3};" \
        : "+f"((d)[0]), "+f"((d)[1]), "+f"((d)[2]), "+f"((d)[3]) \
        : "r"((a)[0]), "r"((a)[1]), "r"((a)[2]), "r"((a)[3]), "r"(b0_), "r"(b1_))

__device__ __forceinline__ float fast_tanh(float v) {
    float e = __expf(2.0f * v);
    return 1.0f - __fdividef(2.0f, e + 1.0f);
}
// hi = bf16 truncation of both floats, packed (1 PRMT)
__device__ __forceinline__ uint32_t packhi(float a, float b) {
    uint32_t r;
    asm("prmt.b32 %0, %1, %2, 0x7632;"
        : "=r"(r) : "r"(__float_as_uint(a)), "r"(__float_as_uint(b)));
    return r;
}
// lo = rn-bf16 of exact residual after truncation
__device__ __forceinline__ uint32_t packlo(float a, float b) {
    float ha = __uint_as_float(__float_as_uint(a) & 0xFFFF0000u);
    float hb = __uint_as_float(__float_as_uint(b) & 0xFFFF0000u);
    __nv_bfloat162 t = __floats2bfloat162_rn(a - ha, b - hb);
    return *(uint32_t*)&t;
}

// values (A+G) -> tanh -> repack as next-step A-frags (registers only)
__device__ __forceinline__ void tanh_pack(const float* A, const float* G,
                                          uint32_t* sh, uint32_t* sl) {
    #pragma unroll
    for (int j = 0; j < 8; ++j) {
        float s0 = fast_tanh(A[4*j+0] + G[4*j+0]);
        float s1 = fast_tanh(A[4*j+1] + G[4*j+1]);
        float s2 = fast_tanh(A[4*j+2] + G[4*j+2]);
        float s3 = fast_tanh(A[4*j+3] + G[4*j+3]);
        const int kt = j >> 1;
        if ((j & 1) == 0) {
            sh[kt*4+0] = packhi(s0, s1); sl[kt*4+0] = packlo(s0, s1);
            sh[kt*4+1] = packhi(s2, s3); sl[kt*4+1] = packlo(s2, s3);
        } else {
            sh[kt*4+2] = packhi(s0, s1); sl[kt*4+2] = packlo(s0, s1);
            sh[kt*4+3] = packhi(s2, s3); sl[kt*4+3] = packlo(s2, s3);
        }
    }
}
__device__ __forceinline__ void tanh_pack0(const float* A, uint32_t* sh, uint32_t* sl) {
    #pragma unroll
    for (int j = 0; j < 8; ++j) {
        float s0 = fast_tanh(A[4*j+0]);
        float s1 = fast_tanh(A[4*j+1]);
        float s2 = fast_tanh(A[4*j+2]);
        float s3 = fast_tanh(A[4*j+3]);
        const int kt = j >> 1;
        if ((j & 1) == 0) {
            sh[kt*4+0] = packhi(s0, s1); sl[kt*4+0] = packlo(s0, s1);
            sh[kt*4+1] = packhi(s2, s3); sl[kt*4+1] = packlo(s2, s3);
        } else {
            sh[kt*4+2] = packhi(s0, s1); sl[kt*4+2] = packlo(s0, s1);
            sh[kt*4+3] = packhi(s2, s3); sl[kt*4+3] = packlo(s2, s3);
        }
    }
}

extern "C" __global__ void __launch_bounds__(NTHR, 1)
narx_frag_kernel(const float* __restrict__ x,
                 const float* __restrict__ W_in,  const float* __restrict__ b_in,
                 const float* __restrict__ W_xh,  const float* __restrict__ W_hh,
                 const float* __restrict__ b_h,   const float* __restrict__ W_out,
                 const float* __restrict__ b_out, float* __restrict__ out)
{
    __shared__ __align__(16) char smp[SM_TOTAL];
    const uint32_t sb = smem_u32(smp);
    const int tid = threadIdx.x, wid = tid >> 5, lane = tid & 31;
    const int gr = lane >> 2, c = lane & 3;
    const int m0 = wid * 16;
    const int cell0 = blockIdx.x * NG;
    const int tb = blockIdx.y * CH;
    const int te = min(tb + CH, NT - 1);
    const int ts = max(tb - (DLY - 1), 0);
    const int emit_lo = max(tb, DLY - 1);

    // ---- prologue: truncation-split weights into smem (hi/lo bf16) ----
    for (int i = tid; i < HID * HID; i += NTHR) {
        int k = i >> 6, n = i & 63;
        float w1 = W_xh[i];
        uint32_t h1 = __float_as_uint(w1) & 0xFFFF0000u;
        ((uint16_t*)(smp + SM_WXH_H))[k*72 + n] = (uint16_t)(h1 >> 16);
        ((__nv_bfloat16*)(smp + SM_WXH_L))[k*72 + n] = __float2bfloat16(w1 - __uint_as_float(h1));
        float w2 = W_hh[i];
        uint32_t h2 = __float_as_uint(w2) & 0xFFFF0000u;
        ((uint16_t*)(smp + SM_WHH_H))[k*72 + n] = (uint16_t)(h2 >> 16);
        ((__nv_bfloat16*)(smp + SM_WHH_L))[k*72 + n] = __float2bfloat16(w2 - __uint_as_float(h2));
    }
    for (int i = tid; i < NXF * HID; i += NTHR) {
        int k = i >> 6, n = i & 63;
        float w = W_in[i];
        uint32_t h = __float_as_uint(w) & 0xFFFF0000u;
        ((uint16_t*)(smp + SM_WIN_H))[k*72 + n] = (uint16_t)(h >> 16);
        ((__nv_bfloat16*)(smp + SM_WIN_L))[k*72 + n] = __float2bfloat16(w - __uint_as_float(h));
    }
    if (tid < HID) {
        ((float*)(smp + SM_BIN))[tid]  = b_in[tid];
        ((float*)(smp + SM_BH))[tid]   = b_h[tid];
        ((float*)(smp + SM_WOUT))[tid] = W_out[tid];
    }
    const float bout = b_out[0];
    __syncthreads();   // only barrier: smem read-only hereafter

    // per-lane LDSM B addresses
    const uint32_t bOff  = (uint32_t)(((lane & 7) + ((lane >> 3) & 1) * 8) * RS + (lane >> 4) * 16);
    const uint32_t wxh_h = sb + SM_WXH_H + bOff;
    const uint32_t wxh_l = sb + SM_WXH_L + bOff;
    const uint32_t whh_h = sb + SM_WHH_H + bOff;
    const uint32_t whh_l = sb + SM_WHH_L + bOff;
    const uint32_t win_h = sb + SM_WIN_H + bOff;
    const uint32_t win_l = sb + SM_WIN_L + bOff;

    const float* binp = (const float*)(smp + SM_BIN);
    const float* bhp  = (const float*)(smp + SM_BH);
    const float* wop  = (const float*)(smp + SM_WOUT);

    // state A-frags in registers: 3 states x (4kt x 4regs) hi+lo, start at 0
    uint32_t SH[3][16], SL[3][16];
    #pragma unroll
    for (int r = 0; r < 3; ++r)
        #pragma unroll
        for (int q = 0; q < 16; ++q) { SH[r][q] = 0u; SL[r][q] = 0u; }

    // x row pointers for this lane (rows gr, gr+8 of warp's 16 cells)
    const size_t tstride = (size_t)NGRID * NXF;
    const float* xr0 = x + ((size_t)ts * NGRID + cell0 + m0 + gr)     * NXF + 2 * c;
    const float* xr8 = x + ((size_t)ts * NGRID + cell0 + m0 + gr + 8) * NXF + 2 * c;
    float2 xn0 = *(const float2*)(xr0);
    float2 xn1 = *(const float2*)(xr0 + 8);
    float2 xn2 = *(const float2*)(xr8);
    float2 xn3 = *(const float2*)(xr8 + 8);
    xr0 += tstride; xr8 += tstride;

    for (int t = ts; t < te; ++t) {
        // ---- x A-frags ----
        uint32_t xh[4], xl[4];
        xh[0] = packhi(xn0.x, xn0.y); xl[0] = packlo(xn0.x, xn0.y);
        xh[1] = packhi(xn2.x, xn2.y); xl[1] = packlo(xn2.x, xn2.y);
        xh[2] = packhi(xn1.x, xn1.y); xl[2] = packlo(xn1.x, xn1.y);
        xh[3] = packhi(xn3.x, xn3.y); xl[3] = packlo(xn3.x, xn3.y);
        xn0 = *(const float2*)(xr0);
        xn1 = *(const float2*)(xr0 + 8);
        xn2 = *(const float2*)(xr8);
        xn3 = *(const float2*)(xr8 + 8);
        xr0 += tstride; xr8 += tstride;

        // ---- U = relu(x @ W_in + b_in), K=16, 3-term ----
        uint32_t uh[16], ul[16];
        {
            float acc[32];
            #pragma unroll
            for (int i = 0; i < 32; ++i) acc[i] = 0.f;
            #pragma unroll
            for (int ntp = 0; ntp < 4; ++ntp) {
                uint32_t b4[4], c4[4];
                LDSM4T(b4, win_h + ntp * 32);
                LDSM4T(c4, win_l + ntp * 32);
                MMA4(&acc[ntp*8],   xh, b4[0], b4[1]); MMA4(&acc[ntp*8+4], xh, b4[2], b4[3]);
                MMA4(&acc[ntp*8],   xl, b4[0], b4[1]); MMA4(&acc[ntp*8+4], xl, b4[2], b4[3]);
                MMA4(&acc[ntp*8],   xh, c4[0], c4[1]); MMA4(&acc[ntp*8+4], xh, c4[2], c4[3]);
            }
            #pragma unroll
            for (int j = 0; j < 8; ++j) {
                float2 b2 = *(const float2*)&binp[j * 8 + 2 * c];
                float u0 = fmaxf(acc[4*j+0] + b2.x, 0.f);
                float u1 = fmaxf(acc[4*j+1] + b2.y, 0.f);
                float u2 = fmaxf(acc[4*j+2] + b2.x, 0.f);
                float u3 = fmaxf(acc[4*j+3] + b2.y, 0.f);
                const int kt = j >> 1;
                if ((j & 1) == 0) {
                    uh[kt*4+0] = packhi(u0, u1); ul[kt*4+0] = packlo(u0, u1);
                    uh[kt*4+1] = packhi(u2, u3); ul[kt*4+1] = packlo(u2, u3);
                } else {
                    uh[kt*4+2] = packhi(u0, u1); ul[kt*4+2] = packlo(u0, u1);
                    uh[kt*4+3] = packhi(u2, u3); ul[kt*4+3] = packlo(u2, u3);
                }
            }
        }

        // ---- A = U @ Wxh + b_h, K=64, 3-term ----
        float A[32];
        #pragma unroll
        for (int i = 0; i < 32; ++i) A[i] = 0.f;
        #pragma unroll
        for (int kt = 0; kt < 4; ++kt) {
            #pragma unroll
            for (int ntp = 0; ntp < 4; ++ntp) {
                uint32_t b4[4], c4[4];
                LDSM4T(b4, wxh_h + kt * (16 * RS) + ntp * 32);
                LDSM4T(c4, wxh_l + kt * (16 * RS) + ntp * 32);
                MMA4(&A[ntp*8],   &uh[kt*4], b4[0], b4[1]); MMA4(&A[ntp*8+4], &uh[kt*4], b4[2], b4[3]);
                MMA4(&A[ntp*8],   &ul[kt*4], b4[0], b4[1]); MMA4(&A[ntp*8+4], &ul[kt*4], b4[2], b4[3]);
                MMA4(&A[ntp*8],   &uh[kt*4], c4[0], c4[1]); MMA4(&A[ntp*8+4], &uh[kt*4], c4[2], c4[3]);
            }
        }
        #pragma unroll
        for (int j = 0; j < 8; ++j) {
            float2 b2 = *(const float2*)&bhp[j * 8 + 2 * c];
            A[4*j+0] += b2.x; A[4*j+1] += b2.y; A[4*j+2] += b2.x; A[4*j+3] += b2.y;
        }

        // ---- FUSED state GEMMs: G1=S3old@W, G2=S2old@W, G3=S1old@W ----
        // shared B frags, 6 independent accumulator chains per ntp
        float G1[32], G2[32], G3[32];
        #pragma unroll
        for (int i = 0; i < 32; ++i) { G1[i] = 0.f; G2[i] = 0.f; G3[i] = 0.f; }
        #pragma unroll
        for (int kt = 0; kt < 4; ++kt) {
            #pragma unroll
            for (int ntp = 0; ntp < 4; ++ntp) {
                uint32_t b4[4], c4[4];
                LDSM4T(b4, whh_h + kt * (16 * RS) + ntp * 32);
                LDSM4T(c4, whh_l + kt * (16 * RS) + ntp * 32);
                MMA4(&G1[ntp*8],   &SH[2][kt*4], b4[0], b4[1]); MMA4(&G1[ntp*8+4], &SH[2][kt*4], b4[2], b4[3]);
                MMA4(&G2[ntp*8],   &SH[1][kt*4], b4[0], b4[1]); MMA4(&G2[ntp*8+4], &SH[1][kt*4], b4[2], b4[3]);
                MMA4(&G3[ntp*8],   &SH[0][kt*4], b4[0], b4[1]); MMA4(&G3[ntp*8+4], &SH[0][kt*4], b4[2], b4[3]);
                MMA4(&G1[ntp*8],   &SL[2][kt*4], b4[0], b4[1]); MMA4(&G1[ntp*8+4], &SL[2][kt*4], b4[2], b4[3]);
                MMA4(&G2[ntp*8],   &SL[1][kt*4], b4[0], b4[1]); MMA4(&G2[ntp*8+4], &SL[1][kt*4], b4[2], b4[3]);
                MMA4(&G3[ntp*8],   &SL[0][kt*4], b4[0], b4[1]); MMA4(&G3[ntp*8+4], &SL[0][kt*4], b4[2], b4[3]);
                MMA4(&G1[ntp*8],   &SH[2][kt*4], c4[0], c4[1]); MMA4(&G1[ntp*8+4], &SH[2][kt*4], c4[2], c4[3]);
                MMA4(&G2[ntp*8],   &SH[1][kt*4], c4[0], c4[1]); MMA4(&G2[ntp*8+4], &SH[1][kt*4], c4[2], c4[3]);
                MMA4(&G3[ntp*8],   &SH[0][kt*4], c4[0], c4[1]); MMA4(&G3[ntp*8+4], &SH[0][kt*4], c4[2], c4[3]);
            }
        }

        // ---- epilogue: y from G1; S3new=tanh(A+G2); S2new=tanh(A+G3); S1new=tanh(A) ----
        float p = 0.f, p8 = 0.f;
        #pragma unroll
        for (int j = 0; j < 8; ++j) {
            float2 w2 = *(const float2*)&wop[j * 8 + 2 * c];
            p  += fast_tanh(A[4*j+0] + G1[4*j+0]) * w2.x
                + fast_tanh(A[4*j+1] + G1[4*j+1]) * w2.y;
            p8 += fast_tanh(A[4*j+2] + G1[4*j+2]) * w2.x
                + fast_tanh(A[4*j+3] + G1[4*j+3]) * w2.y;
        }
        tanh_pack(A, G2, SH[2], SL[2]);
        tanh_pack(A, G3, SH[1], SL[1]);
        tanh_pack0(A, SH[0], SL[0]);

        // ---- emit y ----
        p  += __shfl_xor_sync(0xffffffffu, p, 1);
        p  += __shfl_xor_sync(0xffffffffu, p, 2);
        p8 += __shfl_xor_sync(0xffffffffu, p8, 1);
        p8 += __shfl_xor_sync(0xffffffffu, p8, 2);
        if (c == 0 && t >= emit_lo) {
            size_t base = (size_t)(t + 1) * NGRID + cell0 + m0;
            out[base + gr]     = p  + bout;
            out[base + gr + 8] = p8 + bout;
        }
    }
}

extern "C" __global__ void narx_zero_head(float* __restrict__ out) {
    int i = blockIdx.x * blockDim.x + threadIdx.x;
    if (i < DLY * NGRID) out[i] = 0.f;
}

extern "C" void kernel_launch(void* const* d_in, const int* in_sizes, int n_in,
                              void* d_out, int out_size) {
    const float* x     = (const float*)d_in[0];
    const float* W_in  = (const float*)d_in[1];
    const float* b_in  = (const float*)d_in[2];
    const float* W_xh  = (const float*)d_in[3];
    const float* W_hh  = (const float*)d_in[4];
    const float* b_h   = (const float*)d_in[5];
    const float* W_out = (const float*)d_in[6];
    const float* b_out = (const float*)d_in[7];
    float* out = (float*)d_out;

    narx_zero_head<<<(DLY * NGRID + 255) / 256, 256>>>(out);

    dim3 grid(NGRID / NG, TCH);
    narx_frag_kernel<<<grid, NTHR>>>(
        x, W_in, b_in, W_xh, W_hh, b_h, W_out, b_out, out);
}